// round 5
// baseline (speedup 1.0000x reference)
#include <cuda_runtime.h>
#include <math.h>

// Problem constants (fixed by the reference)
#define B_ROWS 16
#define D_LEN  2097152              // floats per row
#define D4     (D_LEN / 4)          // 524288 float4 per row
#define TPB    256
#define BPR    64                   // 16*64 = 1024 blocks -> single wave @ occ 8
#define NBLK   (BPR * B_ROWS)       // 1024 total blocks
#define STRIDE (BPR * TPB)          // 16384 float4
#define OUTER  16                   // 16 iters x 2 float4 = 32 float4/thread
// D4 = OUTER * 2 * STRIDE = 16*2*16384 = 524288  ✓

// Scratch (zero-initialized at module load; last block resets after use so
// every graph replay starts from the same state — deterministic).
__device__ float        g_rowsum[B_ROWS];
__device__ unsigned int g_arrived;

__global__ __launch_bounds__(TPB, 8) void euclid_loss_kernel(
    const float* __restrict__ outp, const float* __restrict__ labp,
    float* __restrict__ dst)
{
    const int row = blockIdx.y;

    // Per-thread base pointers; second load of each operand uses a constant
    // element offset (STRIDE) so it compiles to an immediate-offset LDG.
    const float4* __restrict__ o =
        (const float4*)(outp + (size_t)row * D_LEN) + blockIdx.x * TPB + threadIdx.x;
    const float4* __restrict__ l =
        (const float4*)(labp + (size_t)row * D_LEN) + blockIdx.x * TPB + threadIdx.x;

    float s0 = 0.0f, s1 = 0.0f;

#pragma unroll
    for (int i = 0; i < OUTER; ++i) {
        // 4 independent LDG.128 in flight
        float4 a0 = __ldcs(o);
        float4 a1 = __ldcs(o + STRIDE);
        float4 b0 = __ldcs(l);
        float4 b1 = __ldcs(l + STRIDE);
        o += 2 * STRIDE;
        l += 2 * STRIDE;

        float dx, dy, dz, dw;
        dx = a0.x - b0.x; dy = a0.y - b0.y; dz = a0.z - b0.z; dw = a0.w - b0.w;
        s0 = fmaf(dx, dx, s0); s1 = fmaf(dy, dy, s1);
        s0 = fmaf(dz, dz, s0); s1 = fmaf(dw, dw, s1);

        dx = a1.x - b1.x; dy = a1.y - b1.y; dz = a1.z - b1.z; dw = a1.w - b1.w;
        s0 = fmaf(dx, dx, s0); s1 = fmaf(dy, dy, s1);
        s0 = fmaf(dz, dz, s0); s1 = fmaf(dw, dw, s1);
    }

    float s = s0 + s1;

    // warp reduce
#pragma unroll
    for (int off = 16; off > 0; off >>= 1)
        s += __shfl_down_sync(0xffffffffu, s, off);

    __shared__ float sm[TPB / 32];
    __shared__ bool  last;
    if ((threadIdx.x & 31) == 0) sm[threadIdx.x >> 5] = s;
    __syncthreads();

    if (threadIdx.x < 32) {
        float v = (threadIdx.x < TPB / 32) ? sm[threadIdx.x] : 0.0f;
#pragma unroll
        for (int off = 16; off > 0; off >>= 1)
            v += __shfl_down_sync(0xffffffffu, v, off);
        if (threadIdx.x == 0) {
            atomicAdd(&g_rowsum[row], v);
            __threadfence();  // make row partial globally visible before arrival
            unsigned int prev = atomicAdd(&g_arrived, 1u);
            last = (prev == (unsigned int)(NBLK - 1));
        }
    }
    __syncthreads();

    // Final block: all partials are in g_rowsum (fence+atomic handshake).
    if (last) {
        __threadfence();  // acquire: see all other blocks' g_rowsum adds
        if (threadIdx.x < 32) {
            float v = (threadIdx.x < B_ROWS) ? sqrtf(g_rowsum[threadIdx.x]) : 0.0f;
#pragma unroll
            for (int off = 16; off > 0; off >>= 1)
                v += __shfl_down_sync(0xffffffffu, v, off);
            if (threadIdx.x == 0) dst[0] = v * (1.0f / (float)B_ROWS);
            // Reset scratch for the next graph replay.
            if (threadIdx.x < B_ROWS) g_rowsum[threadIdx.x] = 0.0f;
            if (threadIdx.x == 0)     g_arrived = 0u;
        }
    }
}

extern "C" void kernel_launch(void* const* d_in, const int* in_sizes, int n_in,
                              void* d_out, int out_size)
{
    const float* outp = (const float*)d_in[0];
    const float* labp = (const float*)d_in[1];
    float* dst = (float*)d_out;

    dim3 grid(BPR, B_ROWS);
    euclid_loss_kernel<<<grid, TPB>>>(outp, labp, dst);
}

// round 6
// speedup vs baseline: 1.0243x; 1.0243x over previous
#include <cuda_runtime.h>
#include <math.h>

// Problem constants (fixed by the reference)
#define B_ROWS   16
#define D_LEN    2097152            // floats per row
#define D4       (D_LEN / 4)        // 524288 float4 per row
#define TPB      256
#define GRID_X   37                 // 37*16 = 592 blocks = 4/SM on 148 SMs (fully resident)
#define NBLK     (GRID_X * B_ROWS)  // 592
#define TILE_F4  1024               // float4 per tile (4 per thread)
#define TILES_PR (D4 / TILE_F4)     // 512 tiles per row
#define CTR_PAD  32                 // 32 uints = 128B between row counters

// Scratch (zero-initialized at module load; last block resets everything so
// each graph replay starts from identical state — deterministic).
__device__ float        g_rowsum[B_ROWS];
__device__ unsigned int g_arrived;
__device__ __align__(128) unsigned int g_tilectr[B_ROWS * CTR_PAD];

__global__ __launch_bounds__(TPB, 4) void euclid_loss_kernel(
    const float* __restrict__ outp, const float* __restrict__ labp,
    float* __restrict__ dst)
{
    const int row = blockIdx.y;
    const float4* __restrict__ orow = (const float4*)(outp + (size_t)row * D_LEN);
    const float4* __restrict__ lrow = (const float4*)(labp + (size_t)row * D_LEN);
    unsigned int* ctr = &g_tilectr[row * CTR_PAD];

    __shared__ unsigned int sh_t;
    __shared__ float sm[TPB / 32];
    __shared__ bool  last;

    if (threadIdx.x == 0) sh_t = atomicAdd(ctr, 1u);
    __syncthreads();
    unsigned int t = sh_t;

    float s0 = 0.0f, s1 = 0.0f, s2 = 0.0f, s3 = 0.0f;

    while (t < TILES_PR) {
        __syncthreads();              // everyone has consumed sh_t
        if (threadIdx.x == 0)         // prefetch next tile; latency hides under loads
            sh_t = atomicAdd(ctr, 1u);

        const float4* op = orow + (t * TILE_F4) + threadIdx.x;
        const float4* lp = lrow + (t * TILE_F4) + threadIdx.x;

        // 8 independent LDG.128 front-batched (immediate offsets)
        float4 a0 = __ldcs(op);
        float4 a1 = __ldcs(op + 256);
        float4 a2 = __ldcs(op + 512);
        float4 a3 = __ldcs(op + 768);
        float4 b0 = __ldcs(lp);
        float4 b1 = __ldcs(lp + 256);
        float4 b2 = __ldcs(lp + 512);
        float4 b3 = __ldcs(lp + 768);

        float dx, dy, dz, dw;
        dx = a0.x - b0.x; dy = a0.y - b0.y; dz = a0.z - b0.z; dw = a0.w - b0.w;
        s0 = fmaf(dx, dx, s0); s1 = fmaf(dy, dy, s1);
        s2 = fmaf(dz, dz, s2); s3 = fmaf(dw, dw, s3);

        dx = a1.x - b1.x; dy = a1.y - b1.y; dz = a1.z - b1.z; dw = a1.w - b1.w;
        s0 = fmaf(dx, dx, s0); s1 = fmaf(dy, dy, s1);
        s2 = fmaf(dz, dz, s2); s3 = fmaf(dw, dw, s3);

        dx = a2.x - b2.x; dy = a2.y - b2.y; dz = a2.z - b2.z; dw = a2.w - b2.w;
        s0 = fmaf(dx, dx, s0); s1 = fmaf(dy, dy, s1);
        s2 = fmaf(dz, dz, s2); s3 = fmaf(dw, dw, s3);

        dx = a3.x - b3.x; dy = a3.y - b3.y; dz = a3.z - b3.z; dw = a3.w - b3.w;
        s0 = fmaf(dx, dx, s0); s1 = fmaf(dy, dy, s1);
        s2 = fmaf(dz, dz, s2); s3 = fmaf(dw, dw, s3);

        __syncthreads();              // tid0's new sh_t is visible
        t = sh_t;
    }

    float s = (s0 + s1) + (s2 + s3);

    // warp reduce
#pragma unroll
    for (int off = 16; off > 0; off >>= 1)
        s += __shfl_down_sync(0xffffffffu, s, off);

    if ((threadIdx.x & 31) == 0) sm[threadIdx.x >> 5] = s;
    __syncthreads();

    if (threadIdx.x < 32) {
        float v = (threadIdx.x < TPB / 32) ? sm[threadIdx.x] : 0.0f;
#pragma unroll
        for (int off = 16; off > 0; off >>= 1)
            v += __shfl_down_sync(0xffffffffu, v, off);
        if (threadIdx.x == 0) {
            atomicAdd(&g_rowsum[row], v);
            __threadfence();  // make row partial globally visible before arrival
            unsigned int prev = atomicAdd(&g_arrived, 1u);
            last = (prev == (unsigned int)(NBLK - 1));
        }
    }
    __syncthreads();

    // Final block: all partials are in g_rowsum (fence+atomic handshake).
    if (last) {
        __threadfence();  // acquire: see all other blocks' g_rowsum adds
        if (threadIdx.x < 32) {
            float v = (threadIdx.x < B_ROWS) ? sqrtf(g_rowsum[threadIdx.x]) : 0.0f;
#pragma unroll
            for (int off = 16; off > 0; off >>= 1)
                v += __shfl_down_sync(0xffffffffu, v, off);
            if (threadIdx.x == 0) dst[0] = v * (1.0f / (float)B_ROWS);
            // Reset ALL scratch for the next graph replay.
            if (threadIdx.x < B_ROWS) {
                g_rowsum[threadIdx.x] = 0.0f;
                g_tilectr[threadIdx.x * CTR_PAD] = 0u;
            }
            if (threadIdx.x == 0) g_arrived = 0u;
        }
    }
}

extern "C" void kernel_launch(void* const* d_in, const int* in_sizes, int n_in,
                              void* d_out, int out_size)
{
    const float* outp = (const float*)d_in[0];
    const float* labp = (const float*)d_in[1];
    float* dst = (float*)d_out;

    dim3 grid(GRID_X, B_ROWS);
    euclid_loss_kernel<<<grid, TPB>>>(outp, labp, dst);
}